// round 1
// baseline (speedup 1.0000x reference)
#include <cuda_runtime.h>
#include <math.h>

#define PI_F 3.14159265358979323846

// One thread per output pixel (b, oy, ox); loops over channels.
// blockIdx.y = batch index b; rotation params computed once per block.
__global__ void __launch_bounds__(256) affine_crop_kernel(
    const float* __restrict__ x,      // [B, C, H, W]
    const float* __restrict__ angles, // [B]
    float* __restrict__ out,          // [B, C, S, S]
    int C, int H, int W, int S)
{
    __shared__ float s_c, s_s;
    const int b = blockIdx.y;

    if (threadIdx.x == 0) {
        float rad = angles[b] * (float)(PI_F / 180.0);
        float sn, cs;
        sincosf(rad, &sn, &cs);
        float scale = fabsf(cs) + fabsf(sn);
        s_c = cs / scale;
        s_s = sn / scale;
    }
    __syncthreads();

    const int pix = blockIdx.x * blockDim.x + threadIdx.x;
    const int SS = S * S;
    if (pix >= SS) return;

    const float c = s_c;
    const float s = s_s;

    const int oy = pix / S;
    const int ox = pix - oy * S;

    const float step = 2.0f / (float)S;
    const float xs = ((float)ox + 0.5f) * step - 1.0f;
    const float ys = ((float)oy + 0.5f) * step - 1.0f;

    const float gx = c * xs - s * ys;
    const float gy = s * xs + c * ys;

    const float ix = ((gx + 1.0f) * (float)W - 1.0f) * 0.5f;
    const float iy = ((gy + 1.0f) * (float)H - 1.0f) * 0.5f;

    const float x0f = floorf(ix);
    const float y0f = floorf(iy);
    const int x0 = (int)x0f;
    const int y0 = (int)y0f;
    const int x1 = x0 + 1;
    const int y1 = y0 + 1;

    const float wx1 = ix - x0f;
    const float wx0 = 1.0f - wx1;
    const float wy1 = iy - y0f;
    const float wy0 = 1.0f - wy1;

    const bool inx0 = (x0 >= 0) & (x0 < W);
    const bool inx1 = (x1 >= 0) & (x1 < W);
    const bool iny0 = (y0 >= 0) & (y0 < H);
    const bool iny1 = (y1 >= 0) & (y1 < H);

    // Fold the zero-padding masks into the bilinear weights (branchless).
    const float w00 = (inx0 & iny0) ? (wy0 * wx0) : 0.0f;
    const float w01 = (inx1 & iny0) ? (wy0 * wx1) : 0.0f;
    const float w10 = (inx0 & iny1) ? (wy1 * wx0) : 0.0f;
    const float w11 = (inx1 & iny1) ? (wy1 * wx1) : 0.0f;

    const int x0c = min(max(x0, 0), W - 1);
    const int x1c = min(max(x1, 0), W - 1);
    const int y0c = min(max(y0, 0), H - 1);
    const int y1c = min(max(y1, 0), H - 1);

    const long long i00 = (long long)y0c * W + x0c;
    const long long i01 = (long long)y0c * W + x1c;
    const long long i10 = (long long)y1c * W + x0c;
    const long long i11 = (long long)y1c * W + x1c;

    const float* img = x + (long long)b * C * H * W;
    float* obase = out + (long long)b * C * SS + pix;
    const long long HW = (long long)H * W;

    #pragma unroll 3
    for (int ch = 0; ch < 3; ++ch) {
        const float* p = img + (long long)ch * HW;
        float v = w00 * __ldg(p + i00)
                + w01 * __ldg(p + i01)
                + w10 * __ldg(p + i10)
                + w11 * __ldg(p + i11);
        obase[(long long)ch * SS] = v;
    }
}

extern "C" void kernel_launch(void* const* d_in, const int* in_sizes, int n_in,
                              void* d_out, int out_size)
{
    const float* x = (const float*)d_in[0];
    const float* angles = (const float*)d_in[1];
    // d_in[2] is out_size as a device scalar; we derive S on host instead.
    float* out = (float*)d_out;

    const int B = in_sizes[1];          // number of angles = batch
    const int C = 3;
    const long long hw = (long long)in_sizes[0] / ((long long)B * C);
    const int H = (int)(sqrt((double)hw) + 0.5);
    const int W = H;
    const long long ss = (long long)out_size / ((long long)B * C);
    const int S = (int)(sqrt((double)ss) + 0.5);

    const int threads = 256;
    const int blocks_x = (S * S + threads - 1) / threads;
    dim3 grid(blocks_x, B, 1);
    affine_crop_kernel<<<grid, threads>>>(x, angles, out, C, H, W, S);
}